// round 13
// baseline (speedup 1.0000x reference)
#include <cuda_runtime.h>

#define NB 128   // persistent CTAs (1/SM, co-resident -> spin loops safe)
#define NT 384   // 12 warps: 0-3 L0 full-K, 4-11 L1 half-K pairs
#define TT 2048
#define BB 8
#define HD 512
#define DI 256

// ---------------- device scratch (no cudaMalloc allowed) ----------------
__device__ float g_hA[2 * BB * HD];      // double-buffered h1 broadcast
__device__ float g_hB[2 * BB * HD];      // double-buffered h2 broadcast
__device__ unsigned g_flags[NB];         // periods completed per CTA (4 L2 lines)

__global__ void init_kernel() {
    int i = blockIdx.x * blockDim.x + threadIdx.x;
    int stride = gridDim.x * blockDim.x;
    if (i < NB) g_flags[i] = 0u;
    for (int k = i; k < 2 * BB * HD; k += stride) { g_hA[k] = 0.0f; g_hB[k] = 0.0f; }
}

__device__ __forceinline__ float tanh_mufu(float x) {
    float y;
    asm("tanh.approx.f32 %0, %1;" : "=f"(y) : "f"(x));
    return y;
}
__device__ __forceinline__ float sigm(float x) {
    return fmaf(0.5f, tanh_mufu(0.5f * x), 0.5f);
}

// Packed dual-FMA on the sm_103a f32x2 pipe.
__device__ __forceinline__ void ffma2(unsigned long long& d, unsigned long long a,
                                      unsigned long long b) {
    asm("fma.rn.f32x2 %0, %1, %2, %0;" : "+l"(d) : "l"(a), "l"(b));
}

// Wait until every CTA has completed >= target periods (4 L2 lines, acquire).
__device__ __forceinline__ void poll_flags(int lane, unsigned target) {
    const unsigned* f = g_flags + lane;
    bool ok;
    do {
        unsigned a, b, c, d;
        asm volatile("ld.acquire.gpu.global.b32 %0, [%1];" : "=r"(a) : "l"(f)      : "memory");
        asm volatile("ld.acquire.gpu.global.b32 %0, [%1];" : "=r"(b) : "l"(f + 32) : "memory");
        asm volatile("ld.acquire.gpu.global.b32 %0, [%1];" : "=r"(c) : "l"(f + 64) : "memory");
        asm volatile("ld.acquire.gpu.global.b32 %0, [%1];" : "=r"(d) : "l"(f + 96) : "memory");
        ok = (a >= target) && (b >= target) && (c >= target) && (d >= target);
    } while (!__all_sync(0xffffffffu, ok));
}

// Register-weight dot: acc[g*8+b] += wgt[it][g] (lane's k-slice) * src[b].
template <int NIT, int STR>
__device__ __forceinline__ void dotr(unsigned long long* acc,
                                     const ulonglong2 (*wgt)[4],
                                     const float* __restrict__ src, int lane) {
#pragma unroll
    for (int it = 0; it < NIT; it++) {
        const float* s = src + it * 128 + lane * 4;
#pragma unroll
        for (int b = 0; b < 8; b++) {
            ulonglong2 v = *(const ulonglong2*)(s + b * STR);
#pragma unroll
            for (int g = 0; g < 4; g++) {
                ffma2(acc[g * 8 + b], wgt[it][g].x, v.x);
                ffma2(acc[g * 8 + b], wgt[it][g].y, v.y);
            }
        }
    }
}

// Shared-weight dot: weights streamed from smem (rows ro0..ro0+3 of mat).
template <int KP>
__device__ __forceinline__ void dots(unsigned long long* acc,
                                     const float* __restrict__ mat,
                                     const float* __restrict__ src, int ro0, int lane) {
#pragma unroll
    for (int it = 0; it < KP / 128; it++) {
        const int kb = it * 128 + lane * 4;
        ulonglong2 m[4];
#pragma unroll
        for (int r = 0; r < 4; r++)
            m[r] = *(const ulonglong2*)(mat + (ro0 + r) * KP + kb);
#pragma unroll
        for (int b = 0; b < 8; b++) {
            ulonglong2 v = *(const ulonglong2*)(src + b * KP + kb);
#pragma unroll
            for (int r = 0; r < 4; r++) {
                ffma2(acc[r * 8 + b], m[r].x, v.x);
                ffma2(acc[r * 8 + b], m[r].y, v.y);
            }
        }
    }
}

// Horizontal f32x2 add + 31-shuffle reduce-scatter.
// Lane l ends owning the total for (gate = l>>3, batch = l&7).
__device__ __forceinline__ float hreduce(const unsigned long long* acc, int lane) {
    float av[32];
#pragma unroll
    for (int j = 0; j < 32; j++) {
        unsigned lo, hi;
        asm("mov.b64 {%0,%1}, %2;" : "=r"(lo), "=r"(hi) : "l"(acc[j]));
        av[j] = __uint_as_float(lo) + __uint_as_float(hi);
    }
#pragma unroll
    for (int m = 16; m > 0; m >>= 1) {
        const bool hi = (lane & m) != 0;
#pragma unroll
        for (int j = 0; j < m; j++) {
            float sendv = hi ? av[j] : av[j + m];
            float other = __shfl_xor_sync(0xffffffffu, sendv, m);
            av[j] = (hi ? av[j + m] : av[j]) + other;
        }
    }
    return av[0];
}

// Fused 2-layer wavefront: period p = layer0 step p + layer1 step p-1.
// Warps 0-3: L0 column jl=w, full K (U0 in regs, W0 from smem).
// Warps 4-11: L1 column jl=(w-4)>>1, K-half kh=(w-4)&1 (U1/W1 halves in regs);
// pair partials combined through sPart. 3 warps/SMSP for latency hiding.
__global__ void __launch_bounds__(NT, 1) lstm_fused_kernel(
    const float* __restrict__ x,
    const float* __restrict__ u0W, const float* __restrict__ w0W,
    const float* __restrict__ u0b, const float* __restrict__ w0b,
    const float* __restrict__ u1W, const float* __restrict__ w1W,
    const float* __restrict__ u1b, const float* __restrict__ w1b,
    float* __restrict__ h2seq, float* __restrict__ hh, float* __restrict__ cc)
{
    extern __shared__ float sm[];
    float* sW0   = sm;                    // 16 x 256 (rows jl*4+g) W0 slice
    float* sA    = sW0 + 16 * DI;         // 8*512  h1(p-1) stage
    float* sB    = sA + BB * HD;          // 8*512  h2(p-2) stage
    float* sX    = sB + BB * HD;          // 2 x 8*256  x double buffer
    float* sPart = sX + 2 * BB * DI;      // 8 x 32 L1 pair partials

    const int tid  = threadIdx.x;
    const int bid  = blockIdx.x;
    const int w    = tid >> 5;
    const int lane = tid & 31;
    const bool L0  = (w < 4);
    const int jl   = L0 ? w : ((w - 4) >> 1);
    const int kh   = L0 ? 0 : ((w - 4) & 1);
    const int jg   = bid * 4 + jl;

    // ---- W0 into shared (local row jl*4+g <-> global row g*HD + bid*4+jl) ----
    for (int idx = tid; idx < 16 * DI; idx += NT) {
        int ro = idx >> 8, k = idx & (DI - 1);
        sW0[idx] = w0W[((size_t)(ro & 3) * HD + bid * 4 + (ro >> 2)) * DI + k];
    }

    // ---- register weights ----
    ulonglong2 wA[4][4];   // L0: U0 full K (4 its). L1: U1 K-half (its 0-1).
    ulonglong2 wB[2][4];   // L1 only: W1 K-half.
    if (L0) {
#pragma unroll
        for (int it = 0; it < 4; it++)
#pragma unroll
            for (int g = 0; g < 4; g++)
                wA[it][g] = *(const ulonglong2*)(u0W + (size_t)(g * HD + jg) * HD
                                                 + it * 128 + lane * 4);
    } else {
#pragma unroll
        for (int it = 0; it < 2; it++)
#pragma unroll
            for (int g = 0; g < 4; g++) {
                wA[it][g] = *(const ulonglong2*)(u1W + (size_t)(g * HD + jg) * HD
                                                 + kh * 256 + it * 128 + lane * 4);
                wB[it][g] = *(const ulonglong2*)(w1W + (size_t)(g * HD + jg) * HD
                                                 + kh * 256 + it * 128 + lane * 4);
            }
    }
    float bs0, bs1, bs2, bs3;
    {
        const float* ubp = L0 ? u0b : u1b;
        const float* wbp = L0 ? w0b : w1b;
        bs0 = ubp[0 * HD + jg] + wbp[0 * HD + jg];
        bs1 = ubp[1 * HD + jg] + wbp[1 * HD + jg];
        bs2 = ubp[2 * HD + jg] + wbp[2 * HD + jg];
        bs3 = ubp[3 * HD + jg] + wbp[3 * HD + jg];
    }
    float creg = 0.0f;   // cell state (column jg, batch=lane) on update warps, lanes 0-7

    // ---- stage x(0) into sX buffer 0 ----
    {
        const float4* x4 = (const float4*)x;
        float4* sX4 = (float4*)sX;
        for (int i = tid; i < BB * DI / 4; i += NT)
            sX4[i] = x4[((size_t)(i >> 6) * TT) * 64 + (i & 63)];
    }
    __syncthreads();

    for (int p = 0; p <= TT; p++) {
        // keep x(p+1) L2-resident
        if (p + 1 < TT && tid < 64) {
            const float* pf = x + ((size_t)(tid >> 3) * TT + (p + 1)) * DI + (tid & 7) * 32;
            asm volatile("prefetch.global.L2 [%0];" :: "l"(pf));
        }

        // ---- phase 1: L0 warps fold W0*x into acc (barrier-independent);
        //      warp 11 (L1, no phase-1 work) polls the period-p barrier ----
        unsigned long long acc[32];
#pragma unroll
        for (int j = 0; j < 32; j++) acc[j] = 0ull;
        if (L0 && p < TT)
            dots<DI>(acc, sW0, sX + (p & 1) * (BB * DI), w * 4, lane);
        if (w == 11) poll_flags(lane, (unsigned)p);
        __syncthreads();

        // ---- phase 2: streamed staging (ld.cg -> STS) ----
        {
            const float4* a4 = (const float4*)(g_hA + (p & 1) * (BB * HD));
            const float4* b4 = (const float4*)(g_hB + ((p + 1) & 1) * (BB * HD));
            float4* sA4 = (float4*)sA;
            float4* sB4 = (float4*)sB;
            for (int i = tid; i < BB * HD / 4; i += NT) {
                sA4[i] = __ldcg(a4 + i);
                sB4[i] = __ldcg(b4 + i);
            }
            if (p + 1 < TT) {
                const float4* x4 = (const float4*)x;
                float4* sX4 = (float4*)(sX + ((p + 1) & 1) * (BB * DI));
                for (int i = tid; i < BB * DI / 4; i += NT)
                    sX4[i] = __ldcg(x4 + ((size_t)(i >> 6) * TT + (p + 1)) * 64 + (i & 63));
            }
        }
        __syncthreads();

        // ---- phase 3: recurrent dots + partial reduce ----
        const bool act = L0 ? (p < TT) : (p > 0);
        float v = 0.0f;
        if (act) {
            if (L0) {
                dotr<4, HD>(acc, wA, sA, lane);
            } else {
                dotr<2, HD>(acc, wA, sB + kh * 256, lane);
                dotr<2, HD>(acc, wB, sA + kh * 256, lane);
            }
            v = hreduce(acc, lane);
            if (!L0) sPart[(w - 4) * 32 + lane] = v;
        }
        __syncthreads();

        // ---- combine + cell update (L0 warps 0-3; L1 kh==0 warps 4,6,8,10) ----
        if (act && (L0 || kh == 0)) {
            if (!L0) v += sPart[(w - 3) * 32 + lane];
            v += (lane < 8) ? bs0 : (lane < 16) ? bs1 : (lane < 24) ? bs2 : bs3;

            const int bsel = lane & 7;
            float vi = __shfl_sync(0xffffffffu, v, bsel);
            float vf = __shfl_sync(0xffffffffu, v, bsel + 8);
            float vg = __shfl_sync(0xffffffffu, v, bsel + 16);
            float vo = __shfl_sync(0xffffffffu, v, bsel + 24);

            if (lane < 8) {   // lane = batch
                float iv = sigm(vi);
                float fv = sigm(vf);
                float gv = tanh_mufu(vg);
                float ov = sigm(vo);
                float c = fv * creg + iv * gv;
                creg = c;
                float h = ov * fmaxf(c, 0.0f);   // custom relu nonlinearity
                if (L0) {
                    __stcg(g_hA + ((p + 1) & 1) * (BB * HD) + lane * HD + jg, h);
                    if (p == TT - 1) { hh[lane * HD + jg] = h; cc[lane * HD + jg] = c; }
                } else {
                    const int t1 = p - 1;
                    __stcg(g_hB + (p & 1) * (BB * HD) + lane * HD + jg, h);
                    __stcg(h2seq + ((size_t)lane * TT + t1) * HD + jg, h);
                    if (t1 == TT - 1) {
                        hh[BB * HD + lane * HD + jg] = h;
                        cc[BB * HD + lane * HD + jg] = c;
                    }
                }
            }
        }

        // ---- publish completion of period p ----
        __syncthreads();
        if (tid == 0) {
            unsigned vfl = (unsigned)(p + 1);
            asm volatile("st.release.gpu.global.b32 [%0], %1;"
                         :: "l"(g_flags + bid), "r"(vfl) : "memory");
        }
    }
}

// ---------------- host launch ----------------
extern "C" void kernel_launch(void* const* d_in, const int* in_sizes, int n_in,
                              void* d_out, int out_size) {
    (void)in_sizes; (void)n_in; (void)out_size;
    const float* x   = (const float*)d_in[0];
    const float* w0w = (const float*)d_in[1];
    const float* w0b = (const float*)d_in[2];
    const float* u0w = (const float*)d_in[3];
    const float* u0b = (const float*)d_in[4];
    const float* w1w = (const float*)d_in[5];
    const float* w1b = (const float*)d_in[6];
    const float* u1w = (const float*)d_in[7];
    const float* u1b = (const float*)d_in[8];
    float* out = (float*)d_out;

    const size_t H2 = (size_t)BB * TT * HD;
    float* hh = out + H2;                     // [2, B, H]
    float* cc = hh + 2 * BB * HD;             // [2, B, H]

    const size_t smem = (size_t)(16 * DI + 2 * BB * HD + 2 * BB * DI + 8 * 32)
                        * sizeof(float);      // ~66.5 KB
    cudaFuncSetAttribute(lstm_fused_kernel, cudaFuncAttributeMaxDynamicSharedMemorySize,
                         (int)smem);

    init_kernel<<<32, 256>>>();
    lstm_fused_kernel<<<NB, NT, smem>>>(x, u0w, w0w, u0b, w0b,
                                        u1w, w1w, u1b, w1b,
                                        out, hh, cc);
}

// round 14
// speedup vs baseline: 1.4366x; 1.4366x over previous
#include <cuda_runtime.h>

#define NB 128   // persistent CTAs (1/SM, co-resident -> spin loops safe)
#define NT 384   // 12 warps: 0-3 L0, 4-11 L1 half-K pairs
#define TT 2048
#define BB 8
#define HD 512
#define DI 256

// ---------------- device scratch (no cudaMalloc allowed) ----------------
__device__ float g_hA[2 * BB * HD];      // double-buffered h1 broadcast
__device__ float g_hB[2 * BB * HD];      // double-buffered h2 broadcast
__device__ unsigned g_flags[NB];         // periods completed per CTA (4 L2 lines)

__global__ void init_kernel() {
    int i = blockIdx.x * blockDim.x + threadIdx.x;
    int stride = gridDim.x * blockDim.x;
    if (i < NB) g_flags[i] = 0u;
    for (int k = i; k < 2 * BB * HD; k += stride) { g_hA[k] = 0.0f; g_hB[k] = 0.0f; }
}

__device__ __forceinline__ float tanh_mufu(float x) {
    float y;
    asm("tanh.approx.f32 %0, %1;" : "=f"(y) : "f"(x));
    return y;
}
__device__ __forceinline__ float sigm(float x) {
    return fmaf(0.5f, tanh_mufu(0.5f * x), 0.5f);
}

// Packed dual-FMA on the sm_103a f32x2 pipe.
__device__ __forceinline__ void ffma2(unsigned long long& d, unsigned long long a,
                                      unsigned long long b) {
    asm("fma.rn.f32x2 %0, %1, %2, %0;" : "+l"(d) : "l"(a), "l"(b));
}

// Wait until every CTA has completed >= target periods (4 L2 lines, acquire).
__device__ __forceinline__ void poll_flags(int lane, unsigned target) {
    const unsigned* f = g_flags + lane;
    bool ok;
    do {
        unsigned a, b, c, d;
        asm volatile("ld.acquire.gpu.global.b32 %0, [%1];" : "=r"(a) : "l"(f)      : "memory");
        asm volatile("ld.acquire.gpu.global.b32 %0, [%1];" : "=r"(b) : "l"(f + 32) : "memory");
        asm volatile("ld.acquire.gpu.global.b32 %0, [%1];" : "=r"(c) : "l"(f + 64) : "memory");
        asm volatile("ld.acquire.gpu.global.b32 %0, [%1];" : "=r"(d) : "l"(f + 96) : "memory");
        ok = (a >= target) && (b >= target) && (c >= target) && (d >= target);
    } while (!__all_sync(0xffffffffu, ok));
}

// Register-weight dot: acc[g*8+b] += wgt[it][g] (lane's k-slice) * src[b].
template <int NIT, int STR>
__device__ __forceinline__ void dotr(unsigned long long* acc,
                                     const ulonglong2 (*wgt)[4],
                                     const float* __restrict__ src, int lane) {
#pragma unroll
    for (int it = 0; it < NIT; it++) {
        const float* s = src + it * 128 + lane * 4;
#pragma unroll
        for (int b = 0; b < 8; b++) {
            ulonglong2 v = *(const ulonglong2*)(s + b * STR);
#pragma unroll
            for (int g = 0; g < 4; g++) {
                ffma2(acc[g * 8 + b], wgt[it][g].x, v.x);
                ffma2(acc[g * 8 + b], wgt[it][g].y, v.y);
            }
        }
    }
}

// Shared-weight dot: weights streamed from smem (rows ro0..ro0+3 of mat).
template <int KP>
__device__ __forceinline__ void dots(unsigned long long* acc,
                                     const float* __restrict__ mat,
                                     const float* __restrict__ src, int ro0, int lane) {
#pragma unroll
    for (int it = 0; it < KP / 128; it++) {
        const int kb = it * 128 + lane * 4;
        ulonglong2 m[4];
#pragma unroll
        for (int r = 0; r < 4; r++)
            m[r] = *(const ulonglong2*)(mat + (ro0 + r) * KP + kb);
#pragma unroll
        for (int b = 0; b < 8; b++) {
            ulonglong2 v = *(const ulonglong2*)(src + b * KP + kb);
#pragma unroll
            for (int r = 0; r < 4; r++) {
                ffma2(acc[r * 8 + b], m[r].x, v.x);
                ffma2(acc[r * 8 + b], m[r].y, v.y);
            }
        }
    }
}

// Horizontal f32x2 add + 31-shuffle reduce-scatter.
// Lane l ends owning the total for (gate = l>>3, batch = l&7).
__device__ __forceinline__ float hreduce(const unsigned long long* acc, int lane) {
    float av[32];
#pragma unroll
    for (int j = 0; j < 32; j++) {
        unsigned lo, hi;
        asm("mov.b64 {%0,%1}, %2;" : "=r"(lo), "=r"(hi) : "l"(acc[j]));
        av[j] = __uint_as_float(lo) + __uint_as_float(hi);
    }
#pragma unroll
    for (int m = 16; m > 0; m >>= 1) {
        const bool hi = (lane & m) != 0;
#pragma unroll
        for (int j = 0; j < m; j++) {
            float sendv = hi ? av[j] : av[j + m];
            float other = __shfl_xor_sync(0xffffffffu, sendv, m);
            av[j] = (hi ? av[j + m] : av[j]) + other;
        }
    }
    return av[0];
}

// Fused 2-layer wavefront: period p = layer0 step p + layer1 step p-1.
// Warps 0-3: L0 column w (W0 from smem pre-reduced in phase 1; U0 in regs).
// Warps 4-11: L1 column (w-4)>>1, K-half (w-4)&1 (U1/W1 halves in regs);
// pair partials combined through sPart + a 64-thread named barrier.
__global__ void __launch_bounds__(NT, 1) lstm_fused_kernel(
    const float* __restrict__ x,
    const float* __restrict__ u0W, const float* __restrict__ w0W,
    const float* __restrict__ u0b, const float* __restrict__ w0b,
    const float* __restrict__ u1W, const float* __restrict__ w1W,
    const float* __restrict__ u1b, const float* __restrict__ w1b,
    float* __restrict__ h2seq, float* __restrict__ hh, float* __restrict__ cc)
{
    extern __shared__ float sm[];
    float* sW0   = sm;                    // 16 x 256 (rows jl*4+g) W0 slice
    float* sA    = sW0 + 16 * DI;         // 8*512  h1(p-1) stage
    float* sB    = sA + BB * HD;          // 8*512  h2(p-2) stage
    float* sX    = sB + BB * HD;          // 2 x 8*256  x double buffer
    float* sPart = sX + 2 * BB * DI;      // 4 x 32 L1 pair partials

    const int tid  = threadIdx.x;
    const int bid  = blockIdx.x;
    const int w    = tid >> 5;
    const int lane = tid & 31;
    const bool L0  = (w < 4);
    const int jl   = L0 ? w : ((w - 4) >> 1);
    const int kh   = L0 ? 0 : ((w - 4) & 1);
    const int pair = L0 ? 0 : ((w - 4) >> 1);
    const int jg   = bid * 4 + jl;

    // ---- W0 into shared (local row jl*4+g <-> global row g*HD + bid*4+jl) ----
    for (int idx = tid; idx < 16 * DI; idx += NT) {
        int ro = idx >> 8, k = idx & (DI - 1);
        sW0[idx] = w0W[((size_t)(ro & 3) * HD + bid * 4 + (ro >> 2)) * DI + k];
    }

    // ---- register weights ----
    ulonglong2 wA[4][4];   // L0: U0 full K (4 its). L1: U1 K-half (its 0-1).
    ulonglong2 wB[2][4];   // L1 only: W1 K-half.
    if (L0) {
#pragma unroll
        for (int it = 0; it < 4; it++)
#pragma unroll
            for (int g = 0; g < 4; g++)
                wA[it][g] = *(const ulonglong2*)(u0W + (size_t)(g * HD + jg) * HD
                                                 + it * 128 + lane * 4);
    } else {
#pragma unroll
        for (int it = 0; it < 2; it++)
#pragma unroll
            for (int g = 0; g < 4; g++) {
                wA[it][g] = *(const ulonglong2*)(u1W + (size_t)(g * HD + jg) * HD
                                                 + kh * 256 + it * 128 + lane * 4);
                wB[it][g] = *(const ulonglong2*)(w1W + (size_t)(g * HD + jg) * HD
                                                 + kh * 256 + it * 128 + lane * 4);
            }
    }
    float bs0, bs1, bs2, bs3;
    {
        const float* ubp = L0 ? u0b : u1b;
        const float* wbp = L0 ? w0b : w1b;
        bs0 = ubp[0 * HD + jg] + wbp[0 * HD + jg];
        bs1 = ubp[1 * HD + jg] + wbp[1 * HD + jg];
        bs2 = ubp[2 * HD + jg] + wbp[2 * HD + jg];
        bs3 = ubp[3 * HD + jg] + wbp[3 * HD + jg];
    }
    float creg = 0.0f;   // cell state (column jg, batch=lane) on update warps, lanes 0-7

    // ---- stage x(0) into sX buffer 0 ----
    {
        const float4* x4 = (const float4*)x;
        float4* sX4 = (float4*)sX;
        for (int i = tid; i < BB * DI / 4; i += NT)
            sX4[i] = x4[((size_t)(i >> 6) * TT) * 64 + (i & 63)];
    }
    __syncthreads();

    for (int p = 0; p <= TT; p++) {
        // keep x(p+1) L2-resident
        if (p + 1 < TT && tid < 64) {
            const float* pf = x + ((size_t)(tid >> 3) * TT + (p + 1)) * DI + (tid & 7) * 32;
            asm volatile("prefetch.global.L2 [%0];" :: "l"(pf));
        }

        // ---- phase 1 (all barrier-independent, overlapped):
        //   L0 warps: W0*x pre-reduced to scalar r0 (acc dead before staging)
        //   warps 4-7: stage x(p+1) into the idle parity buffer
        //   warp 11: poll the period-p barrier
        float r0 = 0.0f;
        if (L0) {
            if (p < TT) {
                unsigned long long accx[32];
#pragma unroll
                for (int j = 0; j < 32; j++) accx[j] = 0ull;
                dots<DI>(accx, sW0, sX + (p & 1) * (BB * DI), w * 4, lane);
                r0 = hreduce(accx, lane);
            }
        } else if (w < 8) {
            if (p + 1 < TT) {
                const float4* x4 = (const float4*)x;
                float4* sX4 = (float4*)(sX + ((p + 1) & 1) * (BB * DI));
                int i = (w - 4) * 32 + lane;
#pragma unroll
                for (int r = 0; r < 4; r++, i += 128)
                    sX4[i] = __ldcg(x4 + ((size_t)(i >> 6) * TT + (p + 1)) * 64 + (i & 63));
            }
        } else if (w == 11) {
            poll_flags(lane, (unsigned)p);
        }
        __syncthreads();

        // ---- phase 2: stage recurrent broadcasts (ld.cg -> STS, streamed) ----
        {
            const float4* a4 = (const float4*)(g_hA + (p & 1) * (BB * HD));
            const float4* b4 = (const float4*)(g_hB + ((p + 1) & 1) * (BB * HD));
            float4* sA4 = (float4*)sA;
            float4* sB4 = (float4*)sB;
            for (int i = tid; i < BB * HD / 4; i += NT) {
                sA4[i] = __ldcg(a4 + i);
                sB4[i] = __ldcg(b4 + i);
            }
        }
        __syncthreads();

        // ---- phase 3: recurrent dots + reduce + cell update ----
        const bool act = L0 ? (p < TT) : (p > 0);
        if (L0) {
            if (act) {
                unsigned long long acc[32];
#pragma unroll
                for (int j = 0; j < 32; j++) acc[j] = 0ull;
                dotr<4, HD>(acc, wA, sA, lane);
                float v = hreduce(acc, lane) + r0;

                const int bsel = lane & 7;
                float vi = __shfl_sync(0xffffffffu, v, bsel);
                float vf = __shfl_sync(0xffffffffu, v, bsel + 8);
                float vg = __shfl_sync(0xffffffffu, v, bsel + 16);
                float vo = __shfl_sync(0xffffffffu, v, bsel + 24);
                if (lane < 8) {
                    float iv = sigm(vi + bs0);
                    float fv = sigm(vf + bs1);
                    float gv = tanh_mufu(vg + bs2);
                    float ov = sigm(vo + bs3);
                    float c = fv * creg + iv * gv;
                    creg = c;
                    float h = ov * fmaxf(c, 0.0f);   // custom relu nonlinearity
                    __stcg(g_hA + ((p + 1) & 1) * (BB * HD) + lane * HD + jg, h);
                    if (p == TT - 1) { hh[lane * HD + jg] = h; cc[lane * HD + jg] = c; }
                }
            }
        } else if (act) {
            unsigned long long acc[32];
#pragma unroll
            for (int j = 0; j < 32; j++) acc[j] = 0ull;
            dotr<2, HD>(acc, wA, sB + kh * 256, lane);
            dotr<2, HD>(acc, wB, sA + kh * 256, lane);
            float v = hreduce(acc, lane);

            if (kh == 1) sPart[pair * 32 + lane] = v;
            asm volatile("bar.sync %0, 64;" :: "r"(1 + pair) : "memory");
            if (kh == 0) {
                v += sPart[pair * 32 + lane];
                const int bsel = lane & 7;
                float vi = __shfl_sync(0xffffffffu, v, bsel);
                float vf = __shfl_sync(0xffffffffu, v, bsel + 8);
                float vg = __shfl_sync(0xffffffffu, v, bsel + 16);
                float vo = __shfl_sync(0xffffffffu, v, bsel + 24);
                if (lane < 8) {
                    const int t1 = p - 1;
                    float iv = sigm(vi + bs0);
                    float fv = sigm(vf + bs1);
                    float gv = tanh_mufu(vg + bs2);
                    float ov = sigm(vo + bs3);
                    float c = fv * creg + iv * gv;
                    creg = c;
                    float h = ov * fmaxf(c, 0.0f);
                    __stcg(g_hB + (p & 1) * (BB * HD) + lane * HD + jg, h);
                    __stcg(h2seq + ((size_t)lane * TT + t1) * HD + jg, h);
                    if (t1 == TT - 1) {
                        hh[BB * HD + lane * HD + jg] = h;
                        cc[BB * HD + lane * HD + jg] = c;
                    }
                }
            }
        }

        // ---- publish completion of period p ----
        __syncthreads();
        if (tid == 0) {
            unsigned vfl = (unsigned)(p + 1);
            asm volatile("st.release.gpu.global.b32 [%0], %1;"
                         :: "l"(g_flags + bid), "r"(vfl) : "memory");
        }
    }
}

// ---------------- host launch ----------------
extern "C" void kernel_launch(void* const* d_in, const int* in_sizes, int n_in,
                              void* d_out, int out_size) {
    (void)in_sizes; (void)n_in; (void)out_size;
    const float* x   = (const float*)d_in[0];
    const float* w0w = (const float*)d_in[1];
    const float* w0b = (const float*)d_in[2];
    const float* u0w = (const float*)d_in[3];
    const float* u0b = (const float*)d_in[4];
    const float* w1w = (const float*)d_in[5];
    const float* w1b = (const float*)d_in[6];
    const float* u1w = (const float*)d_in[7];
    const float* u1b = (const float*)d_in[8];
    float* out = (float*)d_out;

    const size_t H2 = (size_t)BB * TT * HD;
    float* hh = out + H2;                     // [2, B, H]
    float* cc = hh + 2 * BB * HD;             // [2, B, H]

    const size_t smem = (size_t)(16 * DI + 2 * BB * HD + 2 * BB * DI + 4 * 32)
                        * sizeof(float);      // ~64.5 KB
    cudaFuncSetAttribute(lstm_fused_kernel, cudaFuncAttributeMaxDynamicSharedMemorySize,
                         (int)smem);

    init_kernel<<<32, 256>>>();
    lstm_fused_kernel<<<NB, NT, smem>>>(x, u0w, w0w, u0b, w0b,
                                        u1w, w1w, u1b, w1b,
                                        out, hh, cc);
}